// round 13
// baseline (speedup 1.0000x reference)
#include <cuda_runtime.h>
#include <cstdint>

#define Bv 256
#define Tv 512
#define Iv 128
#define Hv 256

// ---------------- scratch (device globals; no cudaMalloc allowed) ----------
// h exchange buffers, bf16x2 pairs: [buf][group][slice][row(32)][pp(8)]
// pair p (cols 2p,2p+1) stored at pp=(p&3)*2+(p>>2)  (comb for frag loads)
__device__ __align__(16) unsigned g_h0buf[2][8][16][32][8];
__device__ __align__(16) unsigned g_h1buf[2][8][16][32][8];
__device__ float g_hfinal[Bv * Hv];
__device__ unsigned g_flags[8 * 32];                // one flag per CTA

// ---------------- helpers ---------------------------------------------------
__device__ __forceinline__ unsigned packbf(float lo, float hi) {
    unsigned r;
    asm("cvt.rn.bf16x2.f32 %0, %1, %2;" : "=r"(r) : "f"(hi), "f"(lo));
    return r;
}
__device__ __forceinline__ void mma_bf16(float c[4], unsigned a0, unsigned a1,
                                         unsigned a2, unsigned a3,
                                         unsigned b0, unsigned b1) {
    asm volatile(
        "mma.sync.aligned.m16n8k16.row.col.f32.bf16.bf16.f32 "
        "{%0,%1,%2,%3}, {%4,%5,%6,%7}, {%8,%9}, {%0,%1,%2,%3};"
        : "+f"(c[0]), "+f"(c[1]), "+f"(c[2]), "+f"(c[3])
        : "r"(a0), "r"(a1), "r"(a2), "r"(a3), "r"(b0), "r"(b1));
}
__device__ __forceinline__ float tanhfast(float x) {
    float y;
    asm("tanh.approx.f32 %0, %1;" : "=f"(y) : "f"(x));
    return y;
}
__device__ __forceinline__ float sigm(float x) {
    return fmaf(0.5f, tanhfast(0.5f * x), 0.5f);
}

// ---------------- fully fused 2-layer LSTM (bf16 wavefront) -----------------
// 128 CTAs: bt (8 groups of 32 batch rows) x hs (16 H-slices of 16 cols).
// Round t: L0 step t (x projection fused) + L1 step t-1. ONE wait + ONE
// release per round; h fragments read DIRECTLY from L2 (no SMEM staging).
// SMEM (u32): W1s 16384 | W0i 4096 | Xs 2048 | gates0 2176 | gates1 2176 | 34
__global__ void __launch_bounds__(256, 1) lstm_fused(
    const float* __restrict__ x, const int* __restrict__ lengths,
    const float* __restrict__ W_ih0, const float* __restrict__ W_hh0,
    const float* __restrict__ b_ih0, const float* __restrict__ b_hh0,
    const float* __restrict__ W_ih1, const float* __restrict__ W_hh1,
    const float* __restrict__ b_ih1, const float* __restrict__ b_hh1)
{
    extern __shared__ unsigned smu[];
    unsigned* W1s = smu;                   // [s32][tp8][n8][pp8]
    unsigned* W0i = smu + 16384;           // [s8][tp8][n8][pp8]
    unsigned* Xs  = smu + 20480;           // [s8][row32][pp8]
    float (*gates0)[68] = (float(*)[68])(smu + 22528);
    float (*gates1)[68] = (float(*)[68])(smu + 24704);
    int* slen = (int*)(smu + 26880);
    int* pmax = (int*)(smu + 26912);

    int tid = threadIdx.x, lane = tid & 31, wid = tid >> 5;
    int bt = blockIdx.x & 7;
    int hs = blockIdx.x >> 3;
    int wm = wid & 1, wn = wid >> 1;       // 2(M) x 4(N=gate) warps
    int grp = lane >> 2, tig = lane & 3;
    int arow0 = wm * 16 + grp;

    // ---- W_hh0 B-fragments in registers (bf16 pairs)
    unsigned Wr0[2][16][2];
#pragma unroll
    for (int nt = 0; nt < 2; nt++) {
        int n = wn * 256 + hs * 16 + nt * 8 + grp;
        const float* p = W_hh0 + (long long)n * Hv;
#pragma unroll
        for (int s = 0; s < 16; s++) {
            Wr0[nt][s][0] = packbf(__ldg(p + s * 16 + 2 * tig),
                                   __ldg(p + s * 16 + 2 * tig + 1));
            Wr0[nt][s][1] = packbf(__ldg(p + s * 16 + 2 * tig + 8),
                                   __ldg(p + s * 16 + 2 * tig + 9));
        }
    }

    // ---- stage W1 = [W_ih1 | W_hh1] into SMEM (bf16 pairs, frag layout)
    for (int i = tid; i < 16384; i += 256) {
        int s = i >> 9, tp = (i >> 6) & 7, n = (i >> 3) & 7, pp = i & 7;
        int p = (pp >> 1) + ((pp & 1) << 2);
        int R = (tp >> 1) * 256 + hs * 16 + ((tp & 1) << 3) + n;
        int k = s * 16 + 2 * p;
        float lo, hi;
        if (k < 256) { lo = W_ih1[R * 256 + k]; hi = W_ih1[R * 256 + k + 1]; }
        else         { lo = W_hh1[R * 256 + k - 256]; hi = W_hh1[R * 256 + k - 255]; }
        W1s[i] = packbf(lo, hi);
    }
    // ---- stage W_ih0 slice into SMEM (K=128)
    for (int i = tid; i < 4096; i += 256) {
        int s = i >> 9, tp = (i >> 6) & 7, n = (i >> 3) & 7, pp = i & 7;
        int p = (pp >> 1) + ((pp & 1) << 2);
        int R = (tp >> 1) * 256 + hs * 16 + ((tp & 1) << 3) + n;
        int k = s * 16 + 2 * p;
        W0i[i] = packbf(W_ih0[R * Iv + k], W_ih0[R * Iv + k + 1]);
    }
    if (tid < 32) slen[tid] = lengths[bt * 32 + tid];
    __syncthreads();
    if (tid == 0) {
        int m = 0;
        for (int i = 0; i < 32; i++) m = max(m, slen[i]);
        pmax[0] = m;
    }
    __syncthreads();
    int maxlen = pmax[0];

    unsigned* myflag = g_flags + bt * 32 + hs;
    const unsigned* gflag = g_flags + bt * 32;

    // accumulator-mapped biases
    float bs0[2][2], bs1[2][2];
#pragma unroll
    for (int nt = 0; nt < 2; nt++) {
        int col = wn * 256 + hs * 16 + nt * 8 + 2 * tig;
        bs0[nt][0] = b_ih0[col] + b_hh0[col];
        bs0[nt][1] = b_ih0[col + 1] + b_hh0[col + 1];
        bs1[nt][0] = b_ih1[col] + b_hh1[col];
        bs1[nt][1] = b_ih1[col + 1] + b_hh1[col + 1];
    }

    // epilogue mapping: thread owns (eb, cols 2p8, 2p8+1)
    int eb = tid >> 3, p8 = tid & 7, ej = 2 * p8;
    int pp8 = (p8 & 3) * 2 + (p8 >> 2);
    int mylen = slen[eb];
    float2 hmy0 = make_float2(0.f, 0.f), hmy1 = make_float2(0.f, 0.f);
    float2 c0 = make_float2(0.f, 0.f), c1 = make_float2(0.f, 0.f);

    // x staging mapping
    int xrow = tid >> 3;
    int xpp  = ((tid & 7) & 3) * 2 + ((tid & 7) >> 2);
    const float* xbase = x + (long long)(bt * 32 + xrow) * (Tv * Iv) + 2 * (tid & 7);

    for (int t = 0; t <= maxlen; t++) {
        // ---- 1. LDG x(t) + pack into Xs (no peer dep; hides under wait)
        if (t < maxlen) {
            const float* xp = xbase + t * Iv;
#pragma unroll
            for (int j = 0; j < 8; j++) {
                float2 v = *(const float2*)(xp + 16 * j);
                Xs[j * 256 + xrow * 8 + xpp] = packbf(v.x, v.y);
            }
        }

        // ---- 2. single wait: all 16 peers completed round t-1
        if (t > 0) {
            if (tid < 16) {
                const unsigned* fp = gflag + tid;
                unsigned v;
                do {
                    asm volatile("ld.acquire.gpu.u32 %0, [%1];" : "=r"(v) : "l"(fp));
                } while (v < (unsigned)t);
            }
        }
        __syncthreads();   // covers Xs visibility + wait completion

        // ---- 3. mma phase (h fragments direct from L2)
        float acc0[2][2][4];
        float acc1[4][2][4];
#pragma unroll
        for (int nt = 0; nt < 2; nt++) {
            acc0[0][nt][0] = bs0[nt][0]; acc0[0][nt][1] = bs0[nt][1];
            acc0[0][nt][2] = bs0[nt][0]; acc0[0][nt][3] = bs0[nt][1];
            acc0[1][nt][0] = 0.f; acc0[1][nt][1] = 0.f;
            acc0[1][nt][2] = 0.f; acc0[1][nt][3] = 0.f;
            acc1[0][nt][0] = bs1[nt][0]; acc1[0][nt][1] = bs1[nt][1];
            acc1[0][nt][2] = bs1[nt][0]; acc1[0][nt][3] = bs1[nt][1];
#pragma unroll
            for (int ch = 1; ch < 4; ch++) {
                acc1[ch][nt][0] = 0.f; acc1[ch][nt][1] = 0.f;
                acc1[ch][nt][2] = 0.f; acc1[ch][nt][3] = 0.f;
            }
        }

        // L0 input projection: x(t) @ W_ih0^T  (8 k-steps from SMEM)
        if (t < maxlen) {
#pragma unroll
            for (int s = 0; s < 8; s++) {
                uint2 lo = *(const uint2*)&Xs[s * 256 + arow0 * 8 + 2 * tig];
                uint2 hi = *(const uint2*)&Xs[s * 256 + (arow0 + 8) * 8 + 2 * tig];
#pragma unroll
                for (int nt = 0; nt < 2; nt++) {
                    uint2 wb = *(const uint2*)
                        &W0i[((s * 8 + wn * 2 + nt) * 8 + grp) * 8 + 2 * tig];
                    mma_bf16(acc0[s & 1][nt], lo.x, hi.x, lo.y, hi.y, wb.x, wb.y);
                }
            }
        }
        // h0(t-1): feeds L0 recurrent part AND L1 input part (direct L2)
        if (t > 0) {
            const uint2* hb = (const uint2*)&g_h0buf[(t - 1) & 1][bt][0][0][0];
#pragma unroll
            for (int s = 0; s < 16; s++) {
                uint2 lo = __ldg(hb + s * 128 + arow0 * 4 + tig);
                uint2 hi = __ldg(hb + s * 128 + (arow0 + 8) * 4 + tig);
#pragma unroll
                for (int nt = 0; nt < 2; nt++) {
                    mma_bf16(acc0[s & 1][nt], lo.x, hi.x, lo.y, hi.y,
                             Wr0[nt][s][0], Wr0[nt][s][1]);
                    uint2 wb = *(const uint2*)
                        &W1s[((s * 8 + wn * 2 + nt) * 8 + grp) * 8 + 2 * tig];
                    mma_bf16(acc1[s & 1][nt], lo.x, hi.x, lo.y, hi.y, wb.x, wb.y);
                }
            }
        }
        // h1(t-2) against W_hh1 (direct L2)
        if (t > 1) {
            const uint2* hb = (const uint2*)&g_h1buf[t & 1][bt][0][0][0];
#pragma unroll
            for (int s = 0; s < 16; s++) {
                uint2 lo = __ldg(hb + s * 128 + arow0 * 4 + tig);
                uint2 hi = __ldg(hb + s * 128 + (arow0 + 8) * 4 + tig);
#pragma unroll
                for (int nt = 0; nt < 2; nt++) {
                    uint2 wb = *(const uint2*)
                        &W1s[(((16 + s) * 8 + wn * 2 + nt) * 8 + grp) * 8 + 2 * tig];
                    mma_bf16(acc1[2 + (s & 1)][nt], lo.x, hi.x, lo.y, hi.y, wb.x, wb.y);
                }
            }
        }

        // ---- 4. write gate preacts
#pragma unroll
        for (int nt = 0; nt < 2; nt++) {
            int gcl = wn * 16 + nt * 8 + 2 * tig;
            if (t < maxlen) {
                *(float2*)&gates0[arow0][gcl] = make_float2(
                    acc0[0][nt][0] + acc0[1][nt][0],
                    acc0[0][nt][1] + acc0[1][nt][1]);
                *(float2*)&gates0[arow0 + 8][gcl] = make_float2(
                    acc0[0][nt][2] + acc0[1][nt][2],
                    acc0[0][nt][3] + acc0[1][nt][3]);
            }
            if (t >= 1) {
                *(float2*)&gates1[arow0][gcl] = make_float2(
                    acc1[0][nt][0] + acc1[1][nt][0] + acc1[2][nt][0] + acc1[3][nt][0],
                    acc1[0][nt][1] + acc1[1][nt][1] + acc1[2][nt][1] + acc1[3][nt][1]);
                *(float2*)&gates1[arow0 + 8][gcl] = make_float2(
                    acc1[0][nt][2] + acc1[1][nt][2] + acc1[2][nt][2] + acc1[3][nt][2],
                    acc1[0][nt][3] + acc1[1][nt][3] + acc1[2][nt][3] + acc1[3][nt][3]);
            }
        }
        __syncthreads();

        // ---- 5. epilogues + publish (bf16 pairs)
        if (t < maxlen) {
            if (t < mylen) {
                float2 gi = *(const float2*)&gates0[eb][ej];
                float2 gf = *(const float2*)&gates0[eb][16 + ej];
                float2 gg = *(const float2*)&gates0[eb][32 + ej];
                float2 go = *(const float2*)&gates0[eb][48 + ej];
                float i0 = sigm(gi.x), i1 = sigm(gi.y);
                float f0 = sigm(gf.x), f1 = sigm(gf.y);
                float g0 = tanhfast(gg.x), g1 = tanhfast(gg.y);
                float o0 = sigm(go.x), o1 = sigm(go.y);
                float cn0 = fmaf(f0, c0.x, i0 * g0);
                float cn1 = fmaf(f1, c0.y, i1 * g1);
                c0 = make_float2(cn0, cn1);
                hmy0 = make_float2(o0 * tanhfast(cn0), o1 * tanhfast(cn1));
            }
            g_h0buf[t & 1][bt][hs][eb][pp8] = packbf(hmy0.x, hmy0.y);
        }
        if (t >= 1) {
            if (t - 1 < mylen) {
                float2 gi = *(const float2*)&gates1[eb][ej];
                float2 gf = *(const float2*)&gates1[eb][16 + ej];
                float2 gg = *(const float2*)&gates1[eb][32 + ej];
                float2 go = *(const float2*)&gates1[eb][48 + ej];
                float i0 = sigm(gi.x), i1 = sigm(gi.y);
                float f0 = sigm(gf.x), f1 = sigm(gf.y);
                float g0 = tanhfast(gg.x), g1 = tanhfast(gg.y);
                float o0 = sigm(go.x), o1 = sigm(go.y);
                float cn0 = fmaf(f0, c1.x, i0 * g0);
                float cn1 = fmaf(f1, c1.y, i1 * g1);
                c1 = make_float2(cn0, cn1);
                hmy1 = make_float2(o0 * tanhfast(cn0), o1 * tanhfast(cn1));
            }
            g_h1buf[(t - 1) & 1][bt][hs][eb][pp8] = packbf(hmy1.x, hmy1.y);
        }
        __syncthreads();

        // ---- 6. single release
        if (tid == 0) {
            unsigned nv = (unsigned)(t + 1);
            asm volatile("st.release.gpu.u32 [%0], %1;" :: "l"(myflag), "r"(nv) : "memory");
        }
    }

    // publish final layer-1 hidden state for FC (f32)
    float* d = g_hfinal + (long long)(bt * 32 + eb) * Hv + hs * 16;
    d[ej] = hmy1.x;
    d[ej + 1] = hmy1.y;
}

// ---------------- final FC + softmax (+ flag reset for next replay) ---------
__global__ void fc_softmax(const float* __restrict__ W_fc,
                           const float* __restrict__ b_fc, float* __restrict__ out)
{
    int b = blockIdx.x, lane = threadIdx.x;

    // block 0 resets exchange flags for the NEXT graph replay (zero-init
    // covers the very first call; lstm_fused of this replay is already done)
    if (b == 0) {
        for (int i = lane; i < 256; i += 32) g_flags[i] = 0u;
    }

    float logit[10];
#pragma unroll
    for (int c = 0; c < 10; c++) {
        float s = 0.0f;
        for (int h = lane; h < Hv; h += 32)
            s += g_hfinal[b * Hv + h] * W_fc[c * Hv + h];
#pragma unroll
        for (int o = 16; o; o >>= 1) s += __shfl_down_sync(0xffffffffu, s, o);
        logit[c] = s;
    }
    if (lane == 0) {
        float mx = -1e30f;
#pragma unroll
        for (int c = 0; c < 10; c++) {
            logit[c] += b_fc[c];
            mx = fmaxf(mx, logit[c]);
        }
        float sum = 0.0f;
#pragma unroll
        for (int c = 0; c < 10; c++) {
            logit[c] = expf(logit[c] - mx);
            sum += logit[c];
        }
        float inv = 1.0f / sum;
#pragma unroll
        for (int c = 0; c < 10; c++) out[b * 10 + c] = logit[c] * inv;
    }
}

// ---------------- host launcher ---------------------------------------------
extern "C" void kernel_launch(void* const* d_in, const int* in_sizes, int n_in,
                              void* d_out, int out_size)
{
    const float* x      = (const float*)d_in[0];
    const int*   length = (const int*)d_in[1];
    const float* W_fc   = (const float*)d_in[2];
    const float* b_fc   = (const float*)d_in[3];
    const float* W_ih0  = (const float*)d_in[4];
    const float* W_hh0  = (const float*)d_in[5];
    const float* b_ih0  = (const float*)d_in[6];
    const float* b_hh0  = (const float*)d_in[7];
    const float* W_ih1  = (const float*)d_in[8];
    const float* W_hh1  = (const float*)d_in[9];
    const float* b_ih1  = (const float*)d_in[10];
    const float* b_hh1  = (const float*)d_in[11];
    float* out = (float*)d_out;

    int smem = 26914 * 4;   // ~105.1 KB
    cudaFuncSetAttribute(lstm_fused, cudaFuncAttributeMaxDynamicSharedMemorySize, smem);

    // fully fused 2-layer LSTM (513 wavefront rounds)
    lstm_fused<<<128, 256, smem>>>(x, length, W_ih0, W_hh0, b_ih0, b_hh0,
                                   W_ih1, W_hh1, b_ih1, b_hh1);
    // FC + softmax (also resets flags for the next replay)
    fc_softmax<<<Bv, 32>>>(W_fc, b_fc, out);
}

// round 14
// speedup vs baseline: 1.4362x; 1.4362x over previous
#include <cuda_runtime.h>
#include <cstdint>

#define Bv 256
#define Tv 512
#define Iv 128
#define Hv 256

// ---------------- scratch (device globals; no cudaMalloc allowed) ----------
// h exchange buffers, bf16x2 pairs: [buf][group][slice][row(32)][pp(8)]
// pair p (cols 2p,2p+1) stored at pp=(p&3)*2+(p>>2)  (comb for LDS.64 frags)
__device__ __align__(16) unsigned g_h0buf[2][8][16][32][8];
__device__ __align__(16) unsigned g_h1buf[2][8][16][32][8];
__device__ float g_hfinal[Bv * Hv];
__device__ unsigned g_flags[8 * 32];                // one flag per CTA

// ---------------- helpers ---------------------------------------------------
__device__ __forceinline__ unsigned packbf(float lo, float hi) {
    unsigned r;
    asm("cvt.rn.bf16x2.f32 %0, %1, %2;" : "=r"(r) : "f"(hi), "f"(lo));
    return r;
}
__device__ __forceinline__ void mma_bf16(float c[4], unsigned a0, unsigned a1,
                                         unsigned a2, unsigned a3,
                                         unsigned b0, unsigned b1) {
    asm volatile(
        "mma.sync.aligned.m16n8k16.row.col.f32.bf16.bf16.f32 "
        "{%0,%1,%2,%3}, {%4,%5,%6,%7}, {%8,%9}, {%0,%1,%2,%3};"
        : "+f"(c[0]), "+f"(c[1]), "+f"(c[2]), "+f"(c[3])
        : "r"(a0), "r"(a1), "r"(a2), "r"(a3), "r"(b0), "r"(b1));
}
__device__ __forceinline__ float tanhfast(float x) {
    float y;
    asm("tanh.approx.f32 %0, %1;" : "=f"(y) : "f"(x));
    return y;
}
__device__ __forceinline__ float sigm(float x) {
    return fmaf(0.5f, tanhfast(0.5f * x), 0.5f);
}

// ---------------- fully fused 2-layer LSTM (bf16 wavefront) -----------------
// 128 CTAs: bt (8 groups of 32 batch rows) x hs (16 H-slices of 16 cols).
// Round t: L0 step t (x(t) projection fused) + L1 step t-1.
// ONE wait + ONE release per round; h staged to SMEM with front-batched
// LDG.128 (high MLP), mma reads conflict-free LDS combs. (R11 shape.)
__global__ void __launch_bounds__(256, 1) lstm_fused(
    const float* __restrict__ x, const int* __restrict__ lengths,
    const float* __restrict__ W_ih0, const float* __restrict__ W_hh0,
    const float* __restrict__ b_ih0, const float* __restrict__ b_hh0,
    const float* __restrict__ W_ih1, const float* __restrict__ W_hh1,
    const float* __restrict__ b_ih1, const float* __restrict__ b_hh1)
{
    extern __shared__ unsigned smu[];
    unsigned* W1s = smu;                   // [s32][tp8][n8][pp8]
    unsigned* W0i = smu + 16384;           // [s8][tp8][n8][pp8]
    unsigned* Hs0 = smu + 20480;           // [s16][row32][pp8]
    unsigned* Hs1 = smu + 24576;
    unsigned* Xs  = smu + 28672;           // [s8][row32][pp8]
    float (*gates0)[68] = (float(*)[68])(smu + 30720);
    float (*gates1)[68] = (float(*)[68])(smu + 32896);
    int* slen = (int*)(smu + 35072);
    int* pmax = (int*)(smu + 35104);

    int tid = threadIdx.x, lane = tid & 31, wid = tid >> 5;
    int bt = blockIdx.x & 7;
    int hs = blockIdx.x >> 3;
    int wm = wid & 1, wn = wid >> 1;       // 2(M) x 4(N=gate) warps
    int grp = lane >> 2, tig = lane & 3;
    int arow0 = wm * 16 + grp;

    // ---- W_hh0 B-fragments in registers (bf16 pairs)
    unsigned Wr0[2][16][2];
#pragma unroll
    for (int nt = 0; nt < 2; nt++) {
        int n = wn * 256 + hs * 16 + nt * 8 + grp;
        const float* p = W_hh0 + (long long)n * Hv;
#pragma unroll
        for (int s = 0; s < 16; s++) {
            Wr0[nt][s][0] = packbf(__ldg(p + s * 16 + 2 * tig),
                                   __ldg(p + s * 16 + 2 * tig + 1));
            Wr0[nt][s][1] = packbf(__ldg(p + s * 16 + 2 * tig + 8),
                                   __ldg(p + s * 16 + 2 * tig + 9));
        }
    }

    // ---- stage W1 = [W_ih1 | W_hh1] into SMEM (bf16 pairs, frag layout)
    for (int i = tid; i < 16384; i += 256) {
        int s = i >> 9, tp = (i >> 6) & 7, n = (i >> 3) & 7, pp = i & 7;
        int p = (pp >> 1) + ((pp & 1) << 2);
        int R = (tp >> 1) * 256 + hs * 16 + ((tp & 1) << 3) + n;
        int k = s * 16 + 2 * p;
        float lo, hi;
        if (k < 256) { lo = W_ih1[R * 256 + k]; hi = W_ih1[R * 256 + k + 1]; }
        else         { lo = W_hh1[R * 256 + k - 256]; hi = W_hh1[R * 256 + k - 255]; }
        W1s[i] = packbf(lo, hi);
    }
    // ---- stage W_ih0 slice into SMEM (K=128)
    for (int i = tid; i < 4096; i += 256) {
        int s = i >> 9, tp = (i >> 6) & 7, n = (i >> 3) & 7, pp = i & 7;
        int p = (pp >> 1) + ((pp & 1) << 2);
        int R = (tp >> 1) * 256 + hs * 16 + ((tp & 1) << 3) + n;
        int k = s * 16 + 2 * p;
        W0i[i] = packbf(W_ih0[R * Iv + k], W_ih0[R * Iv + k + 1]);
    }
    if (tid < 32) slen[tid] = lengths[bt * 32 + tid];
    __syncthreads();
    if (tid == 0) {
        int m = 0;
        for (int i = 0; i < 32; i++) m = max(m, slen[i]);
        pmax[0] = m;
    }
    __syncthreads();
    int maxlen = pmax[0];

    unsigned* myflag = g_flags + bt * 32 + hs;
    const unsigned* gflag = g_flags + bt * 32;

    // accumulator-mapped biases
    float bs0[2][2], bs1[2][2];
#pragma unroll
    for (int nt = 0; nt < 2; nt++) {
        int col = wn * 256 + hs * 16 + nt * 8 + 2 * tig;
        bs0[nt][0] = b_ih0[col] + b_hh0[col];
        bs0[nt][1] = b_ih0[col + 1] + b_hh0[col + 1];
        bs1[nt][0] = b_ih1[col] + b_hh1[col];
        bs1[nt][1] = b_ih1[col + 1] + b_hh1[col + 1];
    }

    // epilogue mapping: thread owns (eb, cols 2p8, 2p8+1)
    int eb = tid >> 3, p8 = tid & 7, ej = 2 * p8;
    int pp8 = (p8 & 3) * 2 + (p8 >> 2);
    int mylen = slen[eb];
    float2 hmy0 = make_float2(0.f, 0.f), hmy1 = make_float2(0.f, 0.f);
    float2 c0 = make_float2(0.f, 0.f), c1 = make_float2(0.f, 0.f);

    // x staging mapping
    int xrow = tid >> 3;
    int xpp  = ((tid & 7) & 3) * 2 + ((tid & 7) >> 2);
    const float* xbase = x + (long long)(bt * 32 + xrow) * (Tv * Iv) + 2 * (tid & 7);

    for (int t = 0; t <= maxlen; t++) {
        // ---- 1. LDG x(t) + pack into Xs BEFORE the wait (no peer dep;
        //         prior round's Xs readers synced at last epilogue barrier)
        if (t < maxlen) {
            const float* xp = xbase + t * Iv;
            float2 xr[8];
#pragma unroll
            for (int j = 0; j < 8; j++)
                xr[j] = *(const float2*)(xp + 16 * j);
#pragma unroll
            for (int j = 0; j < 8; j++)
                Xs[j * 256 + xrow * 8 + xpp] = packbf(xr[j].x, xr[j].y);
        }

        // ---- 2. wait: all 16 peers completed round t-1
        if (t > 0) {
            if (tid < 16) {
                const unsigned* fp = gflag + tid;
                unsigned v;
                do {
                    asm volatile("ld.acquire.gpu.u32 %0, [%1];" : "=r"(v) : "l"(fp));
                } while (v < (unsigned)t);
            }
        }
        __syncthreads();

        // ---- 3. stage h tiles into SMEM (front-batched LDG.128, high MLP)
        if (t > 0) {
            const uint4* s4 = (const uint4*)&g_h0buf[(t - 1) & 1][bt][0][0][0];
            uint4* d4 = (uint4*)Hs0;
#pragma unroll
            for (int i = 0; i < 4; i++) d4[tid + i * 256] = s4[tid + i * 256];
        }
        if (t > 1) {
            const uint4* s4 = (const uint4*)&g_h1buf[t & 1][bt][0][0][0];
            uint4* d4 = (uint4*)Hs1;
#pragma unroll
            for (int i = 0; i < 4; i++) d4[tid + i * 256] = s4[tid + i * 256];
        }
        __syncthreads();

        // ---- 4. mma phase (bf16 k16; split accumulator chains)
        float acc0[2][2][4];
        float acc1[4][2][4];
#pragma unroll
        for (int nt = 0; nt < 2; nt++) {
            acc0[0][nt][0] = bs0[nt][0]; acc0[0][nt][1] = bs0[nt][1];
            acc0[0][nt][2] = bs0[nt][0]; acc0[0][nt][3] = bs0[nt][1];
            acc0[1][nt][0] = 0.f; acc0[1][nt][1] = 0.f;
            acc0[1][nt][2] = 0.f; acc0[1][nt][3] = 0.f;
            acc1[0][nt][0] = bs1[nt][0]; acc1[0][nt][1] = bs1[nt][1];
            acc1[0][nt][2] = bs1[nt][0]; acc1[0][nt][3] = bs1[nt][1];
#pragma unroll
            for (int ch = 1; ch < 4; ch++) {
                acc1[ch][nt][0] = 0.f; acc1[ch][nt][1] = 0.f;
                acc1[ch][nt][2] = 0.f; acc1[ch][nt][3] = 0.f;
            }
        }

        // L0 input projection: x(t) @ W_ih0^T  (8 k-steps)
        if (t < maxlen) {
#pragma unroll
            for (int s = 0; s < 8; s++) {
                uint2 lo = *(const uint2*)&Xs[s * 256 + arow0 * 8 + 2 * tig];
                uint2 hi = *(const uint2*)&Xs[s * 256 + (arow0 + 8) * 8 + 2 * tig];
#pragma unroll
                for (int nt = 0; nt < 2; nt++) {
                    uint2 wb = *(const uint2*)
                        &W0i[((s * 8 + wn * 2 + nt) * 8 + grp) * 8 + 2 * tig];
                    mma_bf16(acc0[s & 1][nt], lo.x, hi.x, lo.y, hi.y, wb.x, wb.y);
                }
            }
        }
        // h0(t-1): feeds L0 recurrent part AND L1 input part
        if (t > 0) {
#pragma unroll
            for (int s = 0; s < 16; s++) {
                uint2 lo = *(const uint2*)&Hs0[s * 256 + arow0 * 8 + 2 * tig];
                uint2 hi = *(const uint2*)&Hs0[s * 256 + (arow0 + 8) * 8 + 2 * tig];
#pragma unroll
                for (int nt = 0; nt < 2; nt++) {
                    mma_bf16(acc0[s & 1][nt], lo.x, hi.x, lo.y, hi.y,
                             Wr0[nt][s][0], Wr0[nt][s][1]);
                    uint2 wb = *(const uint2*)
                        &W1s[((s * 8 + wn * 2 + nt) * 8 + grp) * 8 + 2 * tig];
                    mma_bf16(acc1[s & 1][nt], lo.x, hi.x, lo.y, hi.y, wb.x, wb.y);
                }
            }
        }
        // h1(t-2) against W_hh1
        if (t > 1) {
#pragma unroll
            for (int s = 0; s < 16; s++) {
                uint2 lo = *(const uint2*)&Hs1[s * 256 + arow0 * 8 + 2 * tig];
                uint2 hi = *(const uint2*)&Hs1[s * 256 + (arow0 + 8) * 8 + 2 * tig];
#pragma unroll
                for (int nt = 0; nt < 2; nt++) {
                    uint2 wb = *(const uint2*)
                        &W1s[(((16 + s) * 8 + wn * 2 + nt) * 8 + grp) * 8 + 2 * tig];
                    mma_bf16(acc1[2 + (s & 1)][nt], lo.x, hi.x, lo.y, hi.y, wb.x, wb.y);
                }
            }
        }

        // ---- 5. write gate preacts
#pragma unroll
        for (int nt = 0; nt < 2; nt++) {
            int gcl = wn * 16 + nt * 8 + 2 * tig;
            if (t < maxlen) {
                *(float2*)&gates0[arow0][gcl] = make_float2(
                    acc0[0][nt][0] + acc0[1][nt][0],
                    acc0[0][nt][1] + acc0[1][nt][1]);
                *(float2*)&gates0[arow0 + 8][gcl] = make_float2(
                    acc0[0][nt][2] + acc0[1][nt][2],
                    acc0[0][nt][3] + acc0[1][nt][3]);
            }
            if (t >= 1) {
                *(float2*)&gates1[arow0][gcl] = make_float2(
                    acc1[0][nt][0] + acc1[1][nt][0] + acc1[2][nt][0] + acc1[3][nt][0],
                    acc1[0][nt][1] + acc1[1][nt][1] + acc1[2][nt][1] + acc1[3][nt][1]);
                *(float2*)&gates1[arow0 + 8][gcl] = make_float2(
                    acc1[0][nt][2] + acc1[1][nt][2] + acc1[2][nt][2] + acc1[3][nt][2],
                    acc1[0][nt][3] + acc1[1][nt][3] + acc1[2][nt][3] + acc1[3][nt][3]);
            }
        }
        __syncthreads();

        // ---- 6. epilogues + publish (bf16 pairs)
        if (t < maxlen) {
            if (t < mylen) {
                float2 gi = *(const float2*)&gates0[eb][ej];
                float2 gf = *(const float2*)&gates0[eb][16 + ej];
                float2 gg = *(const float2*)&gates0[eb][32 + ej];
                float2 go = *(const float2*)&gates0[eb][48 + ej];
                float i0 = sigm(gi.x), i1 = sigm(gi.y);
                float f0 = sigm(gf.x), f1 = sigm(gf.y);
                float g0 = tanhfast(gg.x), g1 = tanhfast(gg.y);
                float o0 = sigm(go.x), o1 = sigm(go.y);
                float cn0 = fmaf(f0, c0.x, i0 * g0);
                float cn1 = fmaf(f1, c0.y, i1 * g1);
                c0 = make_float2(cn0, cn1);
                hmy0 = make_float2(o0 * tanhfast(cn0), o1 * tanhfast(cn1));
            }
            g_h0buf[t & 1][bt][hs][eb][pp8] = packbf(hmy0.x, hmy0.y);
        }
        if (t >= 1) {
            if (t - 1 < mylen) {
                float2 gi = *(const float2*)&gates1[eb][ej];
                float2 gf = *(const float2*)&gates1[eb][16 + ej];
                float2 gg = *(const float2*)&gates1[eb][32 + ej];
                float2 go = *(const float2*)&gates1[eb][48 + ej];
                float i0 = sigm(gi.x), i1 = sigm(gi.y);
                float f0 = sigm(gf.x), f1 = sigm(gf.y);
                float g0 = tanhfast(gg.x), g1 = tanhfast(gg.y);
                float o0 = sigm(go.x), o1 = sigm(go.y);
                float cn0 = fmaf(f0, c1.x, i0 * g0);
                float cn1 = fmaf(f1, c1.y, i1 * g1);
                c1 = make_float2(cn0, cn1);
                hmy1 = make_float2(o0 * tanhfast(cn0), o1 * tanhfast(cn1));
            }
            g_h1buf[(t - 1) & 1][bt][hs][eb][pp8] = packbf(hmy1.x, hmy1.y);
        }
        __syncthreads();

        // ---- 7. single release
        if (tid == 0) {
            unsigned nv = (unsigned)(t + 1);
            asm volatile("st.release.gpu.u32 [%0], %1;" :: "l"(myflag), "r"(nv) : "memory");
        }
    }

    // publish final layer-1 hidden state for FC (f32)
    float* d = g_hfinal + (long long)(bt * 32 + eb) * Hv + hs * 16;
    d[ej] = hmy1.x;
    d[ej + 1] = hmy1.y;
}

// ---------------- final FC + softmax (8 warps/block; resets flags too) ------
__global__ void __launch_bounds__(256) fc_softmax(
    const float* __restrict__ W_fc, const float* __restrict__ b_fc,
    float* __restrict__ out)
{
    int wid = threadIdx.x >> 5, lane = threadIdx.x & 31;
    int b = blockIdx.x * 8 + wid;

    // block 0 resets exchange flags for the NEXT graph replay (zero-init
    // covers the very first call; lstm_fused of this replay already done)
    if (blockIdx.x == 0 && threadIdx.x < 256 && wid == 0) {
        for (int i = lane; i < 256; i += 32) g_flags[i] = 0u;
    }

    float logit[10];
#pragma unroll
    for (int c = 0; c < 10; c++) {
        float s = 0.0f;
        for (int h = lane; h < Hv; h += 32)
            s += g_hfinal[b * Hv + h] * W_fc[c * Hv + h];
#pragma unroll
        for (int o = 16; o; o >>= 1) s += __shfl_down_sync(0xffffffffu, s, o);
        logit[c] = s;
    }
    if (lane == 0) {
        float mx = -1e30f;
#pragma unroll
        for (int c = 0; c < 10; c++) {
            logit[c] += b_fc[c];
            mx = fmaxf(mx, logit[c]);
        }
        float sum = 0.0f;
#pragma unroll
        for (int c = 0; c < 10; c++) {
            logit[c] = expf(logit[c] - mx);
            sum += logit[c];
        }
        float inv = 1.0f / sum;
#pragma unroll
        for (int c = 0; c < 10; c++) out[b * 10 + c] = logit[c] * inv;
    }
}

// ---------------- host launcher ---------------------------------------------
extern "C" void kernel_launch(void* const* d_in, const int* in_sizes, int n_in,
                              void* d_out, int out_size)
{
    const float* x      = (const float*)d_in[0];
    const int*   length = (const int*)d_in[1];
    const float* W_fc   = (const float*)d_in[2];
    const float* b_fc   = (const float*)d_in[3];
    const float* W_ih0  = (const float*)d_in[4];
    const float* W_hh0  = (const float*)d_in[5];
    const float* b_ih0  = (const float*)d_in[6];
    const float* b_hh0  = (const float*)d_in[7];
    const float* W_ih1  = (const float*)d_in[8];
    const float* W_hh1  = (const float*)d_in[9];
    const float* b_ih1  = (const float*)d_in[10];
    const float* b_hh1  = (const float*)d_in[11];
    float* out = (float*)d_out;

    int smem = 35106 * 4;   // ~137.1 KB
    cudaFuncSetAttribute(lstm_fused, cudaFuncAttributeMaxDynamicSharedMemorySize, smem);

    // fully fused 2-layer LSTM (513 wavefront rounds)
    lstm_fused<<<128, 256, smem>>>(x, length, W_ih0, W_hh0, b_ih0, b_hh0,
                                   W_ih1, W_hh1, b_ih1, b_hh1);
    // FC + softmax (8 batches/block; block 0 also resets flags)
    fc_softmax<<<Bv / 8, 256>>>(W_fc, b_fc, out);
}

// round 15
// speedup vs baseline: 1.5221x; 1.0598x over previous
#include <cuda_runtime.h>
#include <cstdint>

#define Bv 256
#define Tv 512
#define Iv 128
#define Hv 256

// ---------------- scratch (device globals; no cudaMalloc allowed) ----------
// h exchange buffers, bf16x2 pairs: [buf][group][slice][row(32)][pp(8)]
// pair p (cols 2p,2p+1) stored at pp=(p&3)*2+(p>>2)  (comb for LDS.64 frags)
__device__ __align__(16) unsigned g_h0buf[2][8][16][32][8];
__device__ __align__(16) unsigned g_h1buf[2][8][16][32][8];
__device__ float g_hfinal[Bv * Hv];
__device__ unsigned g_flags[8 * 32];                // one flag per CTA

// ---------------- helpers ---------------------------------------------------
__device__ __forceinline__ unsigned packbf(float lo, float hi) {
    unsigned r;
    asm("cvt.rn.bf16x2.f32 %0, %1, %2;" : "=r"(r) : "f"(hi), "f"(lo));
    return r;
}
__device__ __forceinline__ void mma_bf16(float c[4], unsigned a0, unsigned a1,
                                         unsigned a2, unsigned a3,
                                         unsigned b0, unsigned b1) {
    asm volatile(
        "mma.sync.aligned.m16n8k16.row.col.f32.bf16.bf16.f32 "
        "{%0,%1,%2,%3}, {%4,%5,%6,%7}, {%8,%9}, {%0,%1,%2,%3};"
        : "+f"(c[0]), "+f"(c[1]), "+f"(c[2]), "+f"(c[3])
        : "r"(a0), "r"(a1), "r"(a2), "r"(a3), "r"(b0), "r"(b1));
}
__device__ __forceinline__ float tanhfast(float x) {
    float y;
    asm("tanh.approx.f32 %0, %1;" : "=f"(y) : "f"(x));
    return y;
}
__device__ __forceinline__ float sigm(float x) {
    return fmaf(0.5f, tanhfast(0.5f * x), 0.5f);
}

// ---------------- fully fused 2-layer LSTM (bf16 wavefront, R11 shape) ------
// 128 CTAs: bt (8 groups of 32 batch rows) x hs (16 H-slices of 16 cols).
// Round t: L0 step t (x(t) projection fused) + L1 step t-1.
// ONE wait + ONE release per round. x LDG issued before the wait (loads
// only!); pack + h staging happen after the wait (front-batched, high MLP).
__global__ void __launch_bounds__(256, 1) lstm_fused(
    const float* __restrict__ x, const int* __restrict__ lengths,
    const float* __restrict__ W_ih0, const float* __restrict__ W_hh0,
    const float* __restrict__ b_ih0, const float* __restrict__ b_hh0,
    const float* __restrict__ W_ih1, const float* __restrict__ W_hh1,
    const float* __restrict__ b_ih1, const float* __restrict__ b_hh1)
{
    extern __shared__ unsigned smu[];
    unsigned* W1s = smu;                   // [s32][tp8][n8][pp8]
    unsigned* W0i = smu + 16384;           // [s8][tp8][n8][pp8]
    unsigned* Hs0 = smu + 20480;           // [s16][row32][pp8]
    unsigned* Hs1 = smu + 24576;
    unsigned* Xs  = smu + 28672;           // [s8][row32][pp8]
    float (*gates0)[68] = (float(*)[68])(smu + 30720);
    float (*gates1)[68] = (float(*)[68])(smu + 32896);
    int* slen = (int*)(smu + 35072);
    int* pmax = (int*)(smu + 35104);

    int tid = threadIdx.x, lane = tid & 31, wid = tid >> 5;
    int bt = blockIdx.x & 7;
    int hs = blockIdx.x >> 3;
    int wm = wid & 1, wn = wid >> 1;       // 2(M) x 4(N=gate) warps
    int grp = lane >> 2, tig = lane & 3;
    int arow0 = wm * 16 + grp;

    // ---- W_hh0 B-fragments in registers (bf16 pairs)
    unsigned Wr0[2][16][2];
#pragma unroll
    for (int nt = 0; nt < 2; nt++) {
        int n = wn * 256 + hs * 16 + nt * 8 + grp;
        const float* p = W_hh0 + (long long)n * Hv;
#pragma unroll
        for (int s = 0; s < 16; s++) {
            Wr0[nt][s][0] = packbf(__ldg(p + s * 16 + 2 * tig),
                                   __ldg(p + s * 16 + 2 * tig + 1));
            Wr0[nt][s][1] = packbf(__ldg(p + s * 16 + 2 * tig + 8),
                                   __ldg(p + s * 16 + 2 * tig + 9));
        }
    }

    // ---- stage W1 = [W_ih1 | W_hh1] into SMEM (bf16 pairs, frag layout)
    for (int i = tid; i < 16384; i += 256) {
        int s = i >> 9, tp = (i >> 6) & 7, n = (i >> 3) & 7, pp = i & 7;
        int p = (pp >> 1) + ((pp & 1) << 2);
        int R = (tp >> 1) * 256 + hs * 16 + ((tp & 1) << 3) + n;
        int k = s * 16 + 2 * p;
        float lo, hi;
        if (k < 256) { lo = W_ih1[R * 256 + k]; hi = W_ih1[R * 256 + k + 1]; }
        else         { lo = W_hh1[R * 256 + k - 256]; hi = W_hh1[R * 256 + k - 255]; }
        W1s[i] = packbf(lo, hi);
    }
    // ---- stage W_ih0 slice into SMEM (K=128)
    for (int i = tid; i < 4096; i += 256) {
        int s = i >> 9, tp = (i >> 6) & 7, n = (i >> 3) & 7, pp = i & 7;
        int p = (pp >> 1) + ((pp & 1) << 2);
        int R = (tp >> 1) * 256 + hs * 16 + ((tp & 1) << 3) + n;
        int k = s * 16 + 2 * p;
        W0i[i] = packbf(W_ih0[R * Iv + k], W_ih0[R * Iv + k + 1]);
    }
    if (tid < 32) slen[tid] = lengths[bt * 32 + tid];
    __syncthreads();
    if (tid == 0) {
        int m = 0;
        for (int i = 0; i < 32; i++) m = max(m, slen[i]);
        pmax[0] = m;
    }
    __syncthreads();
    int maxlen = pmax[0];

    unsigned* myflag = g_flags + bt * 32 + hs;
    const unsigned* gflag = g_flags + bt * 32;

    // accumulator-mapped biases
    float bs0[2][2], bs1[2][2];
#pragma unroll
    for (int nt = 0; nt < 2; nt++) {
        int col = wn * 256 + hs * 16 + nt * 8 + 2 * tig;
        bs0[nt][0] = b_ih0[col] + b_hh0[col];
        bs0[nt][1] = b_ih0[col + 1] + b_hh0[col + 1];
        bs1[nt][0] = b_ih1[col] + b_hh1[col];
        bs1[nt][1] = b_ih1[col + 1] + b_hh1[col + 1];
    }

    // epilogue mapping: thread owns (eb, cols 2p8, 2p8+1)
    int eb = tid >> 3, p8 = tid & 7, ej = 2 * p8;
    int pp8 = (p8 & 3) * 2 + (p8 >> 2);
    int mylen = slen[eb];
    float2 hmy0 = make_float2(0.f, 0.f), hmy1 = make_float2(0.f, 0.f);
    float2 c0 = make_float2(0.f, 0.f), c1 = make_float2(0.f, 0.f);

    // x staging mapping
    int xrow = tid >> 3;
    int xpp  = ((tid & 7) & 3) * 2 + ((tid & 7) >> 2);
    const float* xbase = x + (long long)(bt * 32 + xrow) * (Tv * Iv) + 2 * (tid & 7);

    for (int t = 0; t <= maxlen; t++) {
        // ---- 1. LDG x(t) into registers ONLY (latency hides under wait)
        float2 xr[8];
        if (t < maxlen) {
            const float* xp = xbase + t * Iv;
#pragma unroll
            for (int j = 0; j < 8; j++)
                xr[j] = *(const float2*)(xp + 16 * j);
        }

        // ---- 2. wait: all 16 peers completed round t-1
        if (t > 0) {
            if (tid < 16) {
                const unsigned* fp = gflag + tid;
                unsigned v;
                do {
                    asm volatile("ld.acquire.gpu.u32 %0, [%1];" : "=r"(v) : "l"(fp));
                } while (v < (unsigned)t);
            }
        }
        __syncthreads();

        // ---- 3. stage h tiles + x tile into SMEM
        if (t > 0) {
            const uint4* s4 = (const uint4*)&g_h0buf[(t - 1) & 1][bt][0][0][0];
            uint4* d4 = (uint4*)Hs0;
#pragma unroll
            for (int i = 0; i < 4; i++) d4[tid + i * 256] = s4[tid + i * 256];
        }
        if (t > 1) {
            const uint4* s4 = (const uint4*)&g_h1buf[t & 1][bt][0][0][0];
            uint4* d4 = (uint4*)Hs1;
#pragma unroll
            for (int i = 0; i < 4; i++) d4[tid + i * 256] = s4[tid + i * 256];
        }
        if (t < maxlen) {
#pragma unroll
            for (int j = 0; j < 8; j++)
                Xs[j * 256 + xrow * 8 + xpp] = packbf(xr[j].x, xr[j].y);
        }
        __syncthreads();

        // ---- 4. mma phase (bf16 k16; split accumulator chains)
        float acc0[2][2][4];
        float acc1[4][2][4];
#pragma unroll
        for (int nt = 0; nt < 2; nt++) {
            acc0[0][nt][0] = bs0[nt][0]; acc0[0][nt][1] = bs0[nt][1];
            acc0[0][nt][2] = bs0[nt][0]; acc0[0][nt][3] = bs0[nt][1];
            acc0[1][nt][0] = 0.f; acc0[1][nt][1] = 0.f;
            acc0[1][nt][2] = 0.f; acc0[1][nt][3] = 0.f;
            acc1[0][nt][0] = bs1[nt][0]; acc1[0][nt][1] = bs1[nt][1];
            acc1[0][nt][2] = bs1[nt][0]; acc1[0][nt][3] = bs1[nt][1];
#pragma unroll
            for (int ch = 1; ch < 4; ch++) {
                acc1[ch][nt][0] = 0.f; acc1[ch][nt][1] = 0.f;
                acc1[ch][nt][2] = 0.f; acc1[ch][nt][3] = 0.f;
            }
        }

        // L0 input projection: x(t) @ W_ih0^T  (8 k-steps)
        if (t < maxlen) {
#pragma unroll
            for (int s = 0; s < 8; s++) {
                uint2 lo = *(const uint2*)&Xs[s * 256 + arow0 * 8 + 2 * tig];
                uint2 hi = *(const uint2*)&Xs[s * 256 + (arow0 + 8) * 8 + 2 * tig];
#pragma unroll
                for (int nt = 0; nt < 2; nt++) {
                    uint2 wb = *(const uint2*)
                        &W0i[((s * 8 + wn * 2 + nt) * 8 + grp) * 8 + 2 * tig];
                    mma_bf16(acc0[s & 1][nt], lo.x, hi.x, lo.y, hi.y, wb.x, wb.y);
                }
            }
        }
        // h0(t-1): feeds L0 recurrent part AND L1 input part
        if (t > 0) {
#pragma unroll
            for (int s = 0; s < 16; s++) {
                uint2 lo = *(const uint2*)&Hs0[s * 256 + arow0 * 8 + 2 * tig];
                uint2 hi = *(const uint2*)&Hs0[s * 256 + (arow0 + 8) * 8 + 2 * tig];
#pragma unroll
                for (int nt = 0; nt < 2; nt++) {
                    mma_bf16(acc0[s & 1][nt], lo.x, hi.x, lo.y, hi.y,
                             Wr0[nt][s][0], Wr0[nt][s][1]);
                    uint2 wb = *(const uint2*)
                        &W1s[((s * 8 + wn * 2 + nt) * 8 + grp) * 8 + 2 * tig];
                    mma_bf16(acc1[s & 1][nt], lo.x, hi.x, lo.y, hi.y, wb.x, wb.y);
                }
            }
        }
        // h1(t-2) against W_hh1
        if (t > 1) {
#pragma unroll
            for (int s = 0; s < 16; s++) {
                uint2 lo = *(const uint2*)&Hs1[s * 256 + arow0 * 8 + 2 * tig];
                uint2 hi = *(const uint2*)&Hs1[s * 256 + (arow0 + 8) * 8 + 2 * tig];
#pragma unroll
                for (int nt = 0; nt < 2; nt++) {
                    uint2 wb = *(const uint2*)
                        &W1s[(((16 + s) * 8 + wn * 2 + nt) * 8 + grp) * 8 + 2 * tig];
                    mma_bf16(acc1[2 + (s & 1)][nt], lo.x, hi.x, lo.y, hi.y, wb.x, wb.y);
                }
            }
        }

        // ---- 5. write gate preacts
#pragma unroll
        for (int nt = 0; nt < 2; nt++) {
            int gcl = wn * 16 + nt * 8 + 2 * tig;
            if (t < maxlen) {
                *(float2*)&gates0[arow0][gcl] = make_float2(
                    acc0[0][nt][0] + acc0[1][nt][0],
                    acc0[0][nt][1] + acc0[1][nt][1]);
                *(float2*)&gates0[arow0 + 8][gcl] = make_float2(
                    acc0[0][nt][2] + acc0[1][nt][2],
                    acc0[0][nt][3] + acc0[1][nt][3]);
            }
            if (t >= 1) {
                *(float2*)&gates1[arow0][gcl] = make_float2(
                    acc1[0][nt][0] + acc1[1][nt][0] + acc1[2][nt][0] + acc1[3][nt][0],
                    acc1[0][nt][1] + acc1[1][nt][1] + acc1[2][nt][1] + acc1[3][nt][1]);
                *(float2*)&gates1[arow0 + 8][gcl] = make_float2(
                    acc1[0][nt][2] + acc1[1][nt][2] + acc1[2][nt][2] + acc1[3][nt][2],
                    acc1[0][nt][3] + acc1[1][nt][3] + acc1[2][nt][3] + acc1[3][nt][3]);
            }
        }
        __syncthreads();

        // ---- 6. epilogues + publish (bf16 pairs)
        if (t < maxlen) {
            if (t < mylen) {
                float2 gi = *(const float2*)&gates0[eb][ej];
                float2 gf = *(const float2*)&gates0[eb][16 + ej];
                float2 gg = *(const float2*)&gates0[eb][32 + ej];
                float2 go = *(const float2*)&gates0[eb][48 + ej];
                float i0 = sigm(gi.x), i1 = sigm(gi.y);
                float f0 = sigm(gf.x), f1 = sigm(gf.y);
                float g0 = tanhfast(gg.x), g1 = tanhfast(gg.y);
                float o0 = sigm(go.x), o1 = sigm(go.y);
                float cn0 = fmaf(f0, c0.x, i0 * g0);
                float cn1 = fmaf(f1, c0.y, i1 * g1);
                c0 = make_float2(cn0, cn1);
                hmy0 = make_float2(o0 * tanhfast(cn0), o1 * tanhfast(cn1));
            }
            g_h0buf[t & 1][bt][hs][eb][pp8] = packbf(hmy0.x, hmy0.y);
        }
        if (t >= 1) {
            if (t - 1 < mylen) {
                float2 gi = *(const float2*)&gates1[eb][ej];
                float2 gf = *(const float2*)&gates1[eb][16 + ej];
                float2 gg = *(const float2*)&gates1[eb][32 + ej];
                float2 go = *(const float2*)&gates1[eb][48 + ej];
                float i0 = sigm(gi.x), i1 = sigm(gi.y);
                float f0 = sigm(gf.x), f1 = sigm(gf.y);
                float g0 = tanhfast(gg.x), g1 = tanhfast(gg.y);
                float o0 = sigm(go.x), o1 = sigm(go.y);
                float cn0 = fmaf(f0, c1.x, i0 * g0);
                float cn1 = fmaf(f1, c1.y, i1 * g1);
                c1 = make_float2(cn0, cn1);
                hmy1 = make_float2(o0 * tanhfast(cn0), o1 * tanhfast(cn1));
            }
            g_h1buf[(t - 1) & 1][bt][hs][eb][pp8] = packbf(hmy1.x, hmy1.y);
        }
        __syncthreads();

        // ---- 7. single release
        if (tid == 0) {
            unsigned nv = (unsigned)(t + 1);
            asm volatile("st.release.gpu.u32 [%0], %1;" :: "l"(myflag), "r"(nv) : "memory");
        }
    }

    // publish final layer-1 hidden state for FC (f32)
    float* d = g_hfinal + (long long)(bt * 32 + eb) * Hv + hs * 16;
    d[ej] = hmy1.x;
    d[ej + 1] = hmy1.y;
}

// ---------------- final FC + softmax (8 warps/block; resets flags too) ------
__global__ void __launch_bounds__(256) fc_softmax(
    const float* __restrict__ W_fc, const float* __restrict__ b_fc,
    float* __restrict__ out)
{
    int wid = threadIdx.x >> 5, lane = threadIdx.x & 31;
    int b = blockIdx.x * 8 + wid;

    // block 0, warp 0 resets exchange flags for the NEXT graph replay
    // (zero-init covers the first call; this replay's lstm is already done)
    if (blockIdx.x == 0 && wid == 0) {
        for (int i = lane; i < 256; i += 32) g_flags[i] = 0u;
    }

    float logit[10];
#pragma unroll
    for (int c = 0; c < 10; c++) {
        float s = 0.0f;
        for (int h = lane; h < Hv; h += 32)
            s += g_hfinal[b * Hv + h] * W_fc[c * Hv + h];
#pragma unroll
        for (int o = 16; o; o >>= 1) s += __shfl_down_sync(0xffffffffu, s, o);
        logit[c] = s;
    }
    if (lane == 0) {
        float mx = -1e30f;
#pragma unroll
        for (int c = 0; c < 10; c++) {
            logit[c] += b_fc[c];
            mx = fmaxf(mx, logit[c]);
        }
        float sum = 0.0f;
#pragma unroll
        for (int c = 0; c < 10; c++) {
            logit[c] = expf(logit[c] - mx);
            sum += logit[c];
        }
        float inv = 1.0f / sum;
#pragma unroll
        for (int c = 0; c < 10; c++) out[b * 10 + c] = logit[c] * inv;
    }
}

// ---------------- host launcher ---------------------------------------------
extern "C" void kernel_launch(void* const* d_in, const int* in_sizes, int n_in,
                              void* d_out, int out_size)
{
    const float* x      = (const float*)d_in[0];
    const int*   length = (const int*)d_in[1];
    const float* W_fc   = (const float*)d_in[2];
    const float* b_fc   = (const float*)d_in[3];
    const float* W_ih0  = (const float*)d_in[4];
    const float* W_hh0  = (const float*)d_in[5];
    const float* b_ih0  = (const float*)d_in[6];
    const float* b_hh0  = (const float*)d_in[7];
    const float* W_ih1  = (const float*)d_in[8];
    const float* W_hh1  = (const float*)d_in[9];
    const float* b_ih1  = (const float*)d_in[10];
    const float* b_hh1  = (const float*)d_in[11];
    float* out = (float*)d_out;

    int smem = 35106 * 4;   // ~137.1 KB
    cudaFuncSetAttribute(lstm_fused, cudaFuncAttributeMaxDynamicSharedMemorySize, smem);

    // fully fused 2-layer LSTM (513 wavefront rounds)
    lstm_fused<<<128, 256, smem>>>(x, length, W_ih0, W_hh0, b_ih0, b_hh0,
                                   W_ih1, W_hh1, b_ih1, b_hh1);
    // FC + softmax (8 batches/block; block 0 also resets flags)
    fc_softmax<<<Bv / 8, 256>>>(W_fc, b_fc, out);
}

// round 16
// speedup vs baseline: 1.6145x; 1.0607x over previous
#include <cuda_runtime.h>
#include <cstdint>

#define Bv 256
#define Tv 512
#define Iv 128
#define Hv 256

// ---------------- scratch (device globals; no cudaMalloc allowed) ----------
// h exchange buffers, bf16x2 pairs: [buf][group16][slice8][row16][idx16]
// pair p (cols 2p,2p+1 of the 32-col slice) stored at
// idx(p) = (p&3)*4 + ((p>>3)&1)*2 + ((p>>2)&1)   (comb for uint2 frag loads)
__device__ __align__(16) unsigned g_h0buf[2][16][8][16][16];
__device__ __align__(16) unsigned g_h1buf[2][16][8][16][16];
__device__ float g_hfinal[Bv * Hv];
__device__ unsigned g_flags[16 * 32];               // one flag per CTA

// ---------------- helpers ---------------------------------------------------
__device__ __forceinline__ unsigned packbf(float lo, float hi) {
    unsigned r;
    asm("cvt.rn.bf16x2.f32 %0, %1, %2;" : "=r"(r) : "f"(hi), "f"(lo));
    return r;
}
__device__ __forceinline__ void mma_bf16(float c[4], unsigned a0, unsigned a1,
                                         unsigned a2, unsigned a3,
                                         unsigned b0, unsigned b1) {
    asm volatile(
        "mma.sync.aligned.m16n8k16.row.col.f32.bf16.bf16.f32 "
        "{%0,%1,%2,%3}, {%4,%5,%6,%7}, {%8,%9}, {%0,%1,%2,%3};"
        : "+f"(c[0]), "+f"(c[1]), "+f"(c[2]), "+f"(c[3])
        : "r"(a0), "r"(a1), "r"(a2), "r"(a3), "r"(b0), "r"(b1));
}
__device__ __forceinline__ float tanhfast(float x) {
    float y;
    asm("tanh.approx.f32 %0, %1;" : "=f"(y) : "f"(x));
    return y;
}
__device__ __forceinline__ float sigm(float x) {
    return fmaf(0.5f, tanhfast(0.5f * x), 0.5f);
}

// ---------------- fully fused 2-layer LSTM (bf16 wavefront) -----------------
// 128 CTAs: g (16 groups of 16 batch rows) x hs (8 H-slices of 32 cols).
// Round t: L0 step t (x(t) projection fused) + L1 step t-1.
// ONE wait + ONE release per round, 8 peers per group. Warp tile M16xN16.
// SMEM (u32): W1s 32768 | W0i 8192 | Hs0 2048 | Hs1 2048 | Xs 1024 |
//             gates0 2112 | gates1 2112 | misc 18    => ~201.3 KB
__global__ void __launch_bounds__(256, 1) lstm_fused(
    const float* __restrict__ x, const int* __restrict__ lengths,
    const float* __restrict__ W_ih0, const float* __restrict__ W_hh0,
    const float* __restrict__ b_ih0, const float* __restrict__ b_hh0,
    const float* __restrict__ W_ih1, const float* __restrict__ W_hh1,
    const float* __restrict__ b_ih1, const float* __restrict__ b_hh1)
{
    extern __shared__ unsigned smu[];
    unsigned* W1s = smu;                   // [s32][tp16][n8][pp8]
    unsigned* W0i = smu + 32768;           // [s8][tp16][n8][pp8]
    unsigned* Hs0 = smu + 40960;           // [sl8][row16][idx16]
    unsigned* Hs1 = smu + 43008;
    unsigned* Xs  = smu + 45056;           // [s8][row16][idx8]
    float (*gates0)[132] = (float(*)[132])(smu + 46080);
    float (*gates1)[132] = (float(*)[132])(smu + 48192);
    int* slen = (int*)(smu + 50304);
    int* pmax = (int*)(smu + 50320);

    int tid = threadIdx.x, lane = tid & 31, wid = tid >> 5;
    int g  = blockIdx.x >> 3;              // batch group 0..15
    int hs = blockIdx.x & 7;               // hidden slice 0..7
    int q = wid >> 1, half = wid & 1;      // warp -> gate q, 16-col half
    int grp = lane >> 2, tig = lane & 3;

    // ---- W_hh0 B-fragments in registers (bf16 pairs)
    unsigned Wr0[2][16][2];
#pragma unroll
    for (int nt = 0; nt < 2; nt++) {
        int n = q * 256 + hs * 32 + half * 16 + nt * 8 + grp;
        const float* p = W_hh0 + (long long)n * Hv;
#pragma unroll
        for (int s = 0; s < 16; s++) {
            Wr0[nt][s][0] = packbf(__ldg(p + s * 16 + 2 * tig),
                                   __ldg(p + s * 16 + 2 * tig + 1));
            Wr0[nt][s][1] = packbf(__ldg(p + s * 16 + 2 * tig + 8),
                                   __ldg(p + s * 16 + 2 * tig + 9));
        }
    }

    // ---- stage W1 = [W_ih1 | W_hh1] into SMEM (bf16 pairs, frag layout)
    for (int i = tid; i < 32768; i += 256) {
        int pp = i & 7, n = (i >> 3) & 7, tp = (i >> 6) & 15, s = i >> 10;
        int lp = (pp >> 1) + ((pp & 1) << 2);
        int R = (tp >> 2) * 256 + hs * 32 + (((tp >> 1) & 1) << 4)
              + ((tp & 1) << 3) + n;
        int k = s * 16 + 2 * lp;
        float lo, hi;
        if (k < 256) { lo = W_ih1[R * 256 + k]; hi = W_ih1[R * 256 + k + 1]; }
        else         { lo = W_hh1[R * 256 + k - 256]; hi = W_hh1[R * 256 + k - 255]; }
        W1s[i] = packbf(lo, hi);
    }
    // ---- stage W_ih0 slice into SMEM (K=128)
    for (int i = tid; i < 8192; i += 256) {
        int pp = i & 7, n = (i >> 3) & 7, tp = (i >> 6) & 15, s = i >> 10;
        int lp = (pp >> 1) + ((pp & 1) << 2);
        int R = (tp >> 2) * 256 + hs * 32 + (((tp >> 1) & 1) << 4)
              + ((tp & 1) << 3) + n;
        int k = s * 16 + 2 * lp;
        W0i[i] = packbf(W_ih0[R * Iv + k], W_ih0[R * Iv + k + 1]);
    }
    if (tid < 16) slen[tid] = lengths[g * 16 + tid];
    __syncthreads();
    if (tid == 0) {
        int m = 0;
        for (int i = 0; i < 16; i++) m = max(m, slen[i]);
        pmax[0] = m;
    }
    __syncthreads();
    int maxlen = pmax[0];

    unsigned* myflag = g_flags + g * 32 + hs;
    const unsigned* gflag = g_flags + g * 32;

    // accumulator-mapped biases
    float bs0[2][2], bs1[2][2];
#pragma unroll
    for (int nt = 0; nt < 2; nt++) {
        int col = q * 256 + hs * 32 + half * 16 + nt * 8 + 2 * tig;
        bs0[nt][0] = b_ih0[col] + b_hh0[col];
        bs0[nt][1] = b_ih0[col + 1] + b_hh0[col + 1];
        bs1[nt][0] = b_ih1[col] + b_hh1[col];
        bs1[nt][1] = b_ih1[col + 1] + b_hh1[col + 1];
    }

    // epilogue mapping: thread owns (eb, cols jp, jp+1) of the 32-col slice
    int eb = tid >> 4, jj = tid & 15, jp = 2 * jj;
    int idxp = (jj & 3) * 4 + ((jj >> 3) & 1) * 2 + ((jj >> 2) & 1);
    int mylen = slen[eb];
    float2 hmy0 = make_float2(0.f, 0.f), hmy1 = make_float2(0.f, 0.f);
    float2 c0 = make_float2(0.f, 0.f), c1 = make_float2(0.f, 0.f);

    // x staging mapping: row = tid>>4, pairs p = (tid&15) + 16j
    int xrow = tid >> 4;
    int xlp  = tid & 7;                                 // p & 7 (const over j)
    int xidx8 = (xlp & 3) * 2 + (xlp >> 2);
    int xs0 = (tid & 15) >> 3;                          // p>>3 base
    const float* xbase = x + (long long)(g * 16 + xrow) * (Tv * Iv) + 2 * (tid & 15);

    for (int t = 0; t <= maxlen; t++) {
        // ---- 1. LDG x(t) into registers ONLY (latency hides under wait)
        float2 xr[4];
        if (t < maxlen) {
            const float* xp = xbase + t * Iv;
#pragma unroll
            for (int j = 0; j < 4; j++)
                xr[j] = *(const float2*)(xp + 32 * j);
        }

        // ---- 2. wait: all 8 peers completed round t-1
        if (t > 0) {
            if (tid < 8) {
                const unsigned* fp = gflag + tid;
                unsigned v;
                do {
                    asm volatile("ld.acquire.gpu.u32 %0, [%1];" : "=r"(v) : "l"(fp));
                } while (v < (unsigned)t);
            }
        }
        __syncthreads();

        // ---- 3. stage h tiles + x tile into SMEM
        if (t > 0) {
            const uint4* s4 = (const uint4*)&g_h0buf[(t - 1) & 1][g][0][0][0];
            uint4* d4 = (uint4*)Hs0;
#pragma unroll
            for (int i = 0; i < 2; i++) d4[tid + i * 256] = s4[tid + i * 256];
        }
        if (t > 1) {
            const uint4* s4 = (const uint4*)&g_h1buf[t & 1][g][0][0][0];
            uint4* d4 = (uint4*)Hs1;
#pragma unroll
            for (int i = 0; i < 2; i++) d4[tid + i * 256] = s4[tid + i * 256];
        }
        if (t < maxlen) {
#pragma unroll
            for (int j = 0; j < 4; j++)
                Xs[(xs0 + 2 * j) * 128 + xrow * 8 + xidx8] = packbf(xr[j].x, xr[j].y);
        }
        __syncthreads();

        // ---- 4. mma phase (bf16 k16; split accumulator chains)
        float acc0[2][2][4];
        float acc1[4][2][4];
#pragma unroll
        for (int nt = 0; nt < 2; nt++) {
            acc0[0][nt][0] = bs0[nt][0]; acc0[0][nt][1] = bs0[nt][1];
            acc0[0][nt][2] = bs0[nt][0]; acc0[0][nt][3] = bs0[nt][1];
            acc0[1][nt][0] = 0.f; acc0[1][nt][1] = 0.f;
            acc0[1][nt][2] = 0.f; acc0[1][nt][3] = 0.f;
            acc1[0][nt][0] = bs1[nt][0]; acc1[0][nt][1] = bs1[nt][1];
            acc1[0][nt][2] = bs1[nt][0]; acc1[0][nt][3] = bs1[nt][1];
#pragma unroll
            for (int ch = 1; ch < 4; ch++) {
                acc1[ch][nt][0] = 0.f; acc1[ch][nt][1] = 0.f;
                acc1[ch][nt][2] = 0.f; acc1[ch][nt][3] = 0.f;
            }
        }

        // L0 input projection: x(t) @ W_ih0^T  (8 k-steps)
        if (t < maxlen) {
#pragma unroll
            for (int s = 0; s < 8; s++) {
                uint2 lo = *(const uint2*)&Xs[s * 128 + grp * 8 + 2 * tig];
                uint2 hi = *(const uint2*)&Xs[s * 128 + (grp + 8) * 8 + 2 * tig];
#pragma unroll
                for (int nt = 0; nt < 2; nt++) {
                    uint2 wb = *(const uint2*)
                        &W0i[((s * 16 + wid * 2 + nt) * 8 + grp) * 8 + 2 * tig];
                    mma_bf16(acc0[s & 1][nt], lo.x, hi.x, lo.y, hi.y, wb.x, wb.y);
                }
            }
        }
        // h0(t-1): feeds L0 recurrent part AND L1 input part
        if (t > 0) {
#pragma unroll
            for (int s = 0; s < 16; s++) {
                int sl = s >> 1, qq = s & 1;
                uint2 lo = *(const uint2*)
                    &Hs0[sl * 256 + grp * 16 + tig * 4 + qq * 2];
                uint2 hi = *(const uint2*)
                    &Hs0[sl * 256 + (grp + 8) * 16 + tig * 4 + qq * 2];
#pragma unroll
                for (int nt = 0; nt < 2; nt++) {
                    mma_bf16(acc0[s & 1][nt], lo.x, hi.x, lo.y, hi.y,
                             Wr0[nt][s][0], Wr0[nt][s][1]);
                    uint2 wb = *(const uint2*)
                        &W1s[((s * 16 + wid * 2 + nt) * 8 + grp) * 8 + 2 * tig];
                    mma_bf16(acc1[s & 1][nt], lo.x, hi.x, lo.y, hi.y, wb.x, wb.y);
                }
            }
        }
        // h1(t-2) against W_hh1
        if (t > 1) {
#pragma unroll
            for (int s = 0; s < 16; s++) {
                int sl = s >> 1, qq = s & 1;
                uint2 lo = *(const uint2*)
                    &Hs1[sl * 256 + grp * 16 + tig * 4 + qq * 2];
                uint2 hi = *(const uint2*)
                    &Hs1[sl * 256 + (grp + 8) * 16 + tig * 4 + qq * 2];
#pragma unroll
                for (int nt = 0; nt < 2; nt++) {
                    uint2 wb = *(const uint2*)
                        &W1s[(((16 + s) * 16 + wid * 2 + nt) * 8 + grp) * 8 + 2 * tig];
                    mma_bf16(acc1[2 + (s & 1)][nt], lo.x, hi.x, lo.y, hi.y, wb.x, wb.y);
                }
            }
        }

        // ---- 5. write gate preacts (16 rows x 128 gate cols)
#pragma unroll
        for (int nt = 0; nt < 2; nt++) {
            int gcl = q * 32 + half * 16 + nt * 8 + 2 * tig;
            if (t < maxlen) {
                *(float2*)&gates0[grp][gcl] = make_float2(
                    acc0[0][nt][0] + acc0[1][nt][0],
                    acc0[0][nt][1] + acc0[1][nt][1]);
                *(float2*)&gates0[grp + 8][gcl] = make_float2(
                    acc0[0][nt][2] + acc0[1][nt][2],
                    acc0[0][nt][3] + acc0[1][nt][3]);
            }
            if (t >= 1) {
                *(float2*)&gates1[grp][gcl] = make_float2(
                    acc1[0][nt][0] + acc1[1][nt][0] + acc1[2][nt][0] + acc1[3][nt][0],
                    acc1[0][nt][1] + acc1[1][nt][1] + acc1[2][nt][1] + acc1[3][nt][1]);
                *(float2*)&gates1[grp + 8][gcl] = make_float2(
                    acc1[0][nt][2] + acc1[1][nt][2] + acc1[2][nt][2] + acc1[3][nt][2],
                    acc1[0][nt][3] + acc1[1][nt][3] + acc1[2][nt][3] + acc1[3][nt][3]);
            }
        }
        __syncthreads();

        // ---- 6. epilogues + publish (bf16 pairs)
        if (t < maxlen) {
            if (t < mylen) {
                float2 gi = *(const float2*)&gates0[eb][jp];
                float2 gf = *(const float2*)&gates0[eb][32 + jp];
                float2 gg = *(const float2*)&gates0[eb][64 + jp];
                float2 go = *(const float2*)&gates0[eb][96 + jp];
                float i0 = sigm(gi.x), i1 = sigm(gi.y);
                float f0 = sigm(gf.x), f1 = sigm(gf.y);
                float g0 = tanhfast(gg.x), g1 = tanhfast(gg.y);
                float o0 = sigm(go.x), o1 = sigm(go.y);
                float cn0 = fmaf(f0, c0.x, i0 * g0);
                float cn1 = fmaf(f1, c0.y, i1 * g1);
                c0 = make_float2(cn0, cn1);
                hmy0 = make_float2(o0 * tanhfast(cn0), o1 * tanhfast(cn1));
            }
            g_h0buf[t & 1][g][hs][eb][idxp] = packbf(hmy0.x, hmy0.y);
        }
        if (t >= 1) {
            if (t - 1 < mylen) {
                float2 gi = *(const float2*)&gates1[eb][jp];
                float2 gf = *(const float2*)&gates1[eb][32 + jp];
                float2 gg = *(const float2*)&gates1[eb][64 + jp];
                float2 go = *(const float2*)&gates1[eb][96 + jp];
                float i0 = sigm(gi.x), i1 = sigm(gi.y);
                float f0 = sigm(gf.x), f1 = sigm(gf.y);
                float g0 = tanhfast(gg.x), g1 = tanhfast(gg.y);
                float o0 = sigm(go.x), o1 = sigm(go.y);
                float cn0 = fmaf(f0, c1.x, i0 * g0);
                float cn1 = fmaf(f1, c1.y, i1 * g1);
                c1 = make_float2(cn0, cn1);
                hmy1 = make_float2(o0 * tanhfast(cn0), o1 * tanhfast(cn1));
            }
            g_h1buf[(t - 1) & 1][g][hs][eb][idxp] = packbf(hmy1.x, hmy1.y);
        }
        __syncthreads();

        // ---- 7. single release
        if (tid == 0) {
            unsigned nv = (unsigned)(t + 1);
            asm volatile("st.release.gpu.u32 [%0], %1;" :: "l"(myflag), "r"(nv) : "memory");
        }
    }

    // publish final layer-1 hidden state for FC (f32)
    float* d = g_hfinal + (long long)(g * 16 + eb) * Hv + hs * 32;
    d[jp] = hmy1.x;
    d[jp + 1] = hmy1.y;
}

// ---------------- final FC + softmax (8 warps/block; resets flags too) ------
__global__ void __launch_bounds__(256) fc_softmax(
    const float* __restrict__ W_fc, const float* __restrict__ b_fc,
    float* __restrict__ out)
{
    int wid = threadIdx.x >> 5, lane = threadIdx.x & 31;
    int b = blockIdx.x * 8 + wid;

    // block 0, warp 0 resets exchange flags for the NEXT graph replay
    // (zero-init covers the first call; this replay's lstm is already done)
    if (blockIdx.x == 0 && wid == 0) {
        for (int i = lane; i < 512; i += 32) g_flags[i] = 0u;
    }

    float logit[10];
#pragma unroll
    for (int c = 0; c < 10; c++) {
        float s = 0.0f;
        for (int h = lane; h < Hv; h += 32)
            s += g_hfinal[b * Hv + h] * W_fc[c * Hv + h];
#pragma unroll
        for (int o = 16; o; o >>= 1) s += __shfl_down_sync(0xffffffffu, s, o);
        logit[c] = s;
    }
    if (lane == 0) {
        float mx = -1e30f;
#pragma unroll
        for (int c = 0; c < 10; c++) {
            logit[c] += b_fc[c];
            mx = fmaxf(mx, logit[c]);
        }
        float sum = 0.0f;
#pragma unroll
        for (int c = 0; c < 10; c++) {
            logit[c] = expf(logit[c] - mx);
            sum += logit[c];
        }
        float inv = 1.0f / sum;
#pragma unroll
        for (int c = 0; c < 10; c++) out[b * 10 + c] = logit[c] * inv;
    }
}

// ---------------- host launcher ---------------------------------------------
extern "C" void kernel_launch(void* const* d_in, const int* in_sizes, int n_in,
                              void* d_out, int out_size)
{
    const float* x      = (const float*)d_in[0];
    const int*   length = (const int*)d_in[1];
    const float* W_fc   = (const float*)d_in[2];
    const float* b_fc   = (const float*)d_in[3];
    const float* W_ih0  = (const float*)d_in[4];
    const float* W_hh0  = (const float*)d_in[5];
    const float* b_ih0  = (const float*)d_in[6];
    const float* b_hh0  = (const float*)d_in[7];
    const float* W_ih1  = (const float*)d_in[8];
    const float* W_hh1  = (const float*)d_in[9];
    const float* b_ih1  = (const float*)d_in[10];
    const float* b_hh1  = (const float*)d_in[11];
    float* out = (float*)d_out;

    int smem = 50322 * 4;   // ~201.3 KB
    cudaFuncSetAttribute(lstm_fused, cudaFuncAttributeMaxDynamicSharedMemorySize, smem);

    // fully fused 2-layer LSTM (wavefront rounds; 16 groups x 8 peers)
    lstm_fused<<<128, 256, smem>>>(x, length, W_ih0, W_hh0, b_ih0, b_hh0,
                                   W_ih1, W_hh1, b_ih1, b_hh1);
    // FC + softmax (8 batches/block; block 0 also resets flags)
    fc_softmax<<<Bv / 8, 256>>>(W_fc, b_fc, out);
}